// round 10
// baseline (speedup 1.0000x reference)
#include <cuda_runtime.h>
#include <cuda_fp16.h>
#include <cstdint>

// N=65536, K=256, D=512, ALPHA=1, fp32 in/out.
#define D_DIM  512
#define K_CL   256
#define BM     128
#define KC     64
#define NCHUNK 8
#define CB_CHUNK_BYTES (K_CL * KC * 2)   // 32768

// smem byte offsets
#define OFF_A0   0        // 128 x 128B = 16384
#define OFF_A1   16384
#define OFF_B0   32768    // 256 x 128B = 32768
#define OFF_B1   65536
#define OFF_C2S  98304    // 256 f32
#define OFF_X2S  99328    // 128 f32
#define OFF_PART 99840    // 128*4 f32
#define OFF_INV  101888   // 128 f32
#define SM_MBAR0 102400
#define SM_MBAR1 102408
#define SMEM_TOTAL 102528

__device__ __align__(128) unsigned char g_cb[NCHUNK * CB_CHUNK_BYTES]; // 256KB f16 swizzled
__device__ float g_c2[K_CL];

__device__ __forceinline__ uint32_t sw128(uint32_t off) { return off ^ ((off >> 3) & 0x70); }

__device__ __forceinline__ uint32_t smem_u32(const void* p) {
    uint32_t a;
    asm("{ .reg .u64 t; cvta.to.shared.u64 t, %1; cvt.u32.u64 %0, t; }" : "=r"(a) : "l"(p));
    return a;
}
__device__ __forceinline__ unsigned long long gptr(const void* p) {
    unsigned long long a;
    asm("cvta.to.global.u64 %0, %1;" : "=l"(a) : "l"(p));
    return a;
}
__device__ __forceinline__ float frcp(float x) {
    float r; asm("rcp.approx.f32 %0, %1;" : "=f"(r) : "f"(x)); return r;
}
__device__ __forceinline__ void ldsm_x4(uint32_t (&r)[4], uint32_t addr) {
    asm volatile("ldmatrix.sync.aligned.m8n8.x4.shared.b16 {%0,%1,%2,%3}, [%4];"
                 : "=r"(r[0]), "=r"(r[1]), "=r"(r[2]), "=r"(r[3]) : "r"(addr));
}
// f16 accumulate: d/c = 2 b32 regs (4 halves), same thread->element map as fp32 d0..d3
__device__ __forceinline__ void mma16816h(uint32_t (&d)[2], const uint32_t (&a)[4],
                                          uint32_t b0, uint32_t b1) {
    asm volatile("mma.sync.aligned.m16n8k16.row.col.f16.f16.f16.f16 "
                 "{%0,%1}, {%2,%3,%4,%5}, {%6,%7}, {%0,%1};"
                 : "+r"(d[0]), "+r"(d[1])
                 : "r"(a[0]), "r"(a[1]), "r"(a[2]), "r"(a[3]), "r"(b0), "r"(b1));
}

#define MBAR_INIT(a, c) \
    asm volatile("mbarrier.init.shared.b64 [%0], %1;" :: "r"(a), "r"(c) : "memory")
#define MBAR_EXPECT_TX(a, n) \
    asm volatile("mbarrier.arrive.expect_tx.shared.b64 _, [%0], %1;" :: "r"(a), "r"(n) : "memory")
#define BULK_G2S(dst, src, n, mbar) \
    asm volatile("cp.async.bulk.shared::cluster.global.mbarrier::complete_tx::bytes " \
                 "[%0], [%1], %2, [%3];" \
                 :: "r"(dst), "l"(src), "r"(n), "r"(mbar) : "memory")
#define MBAR_WAIT(a, ph) do {                                                        \
    uint32_t _m = (a), _p = (ph), _d;                                                \
    asm volatile("{ .reg .pred p; mbarrier.try_wait.parity.acquire.cta.shared::cta.b64 p, [%1], %2;" \
                 " selp.b32 %0, 1, 0, p; }" : "=r"(_d) : "r"(_m), "r"(_p) : "memory"); \
    if (!_d) {                                                                       \
        asm volatile("{ .reg .pred P1; WL_%=:"                                       \
                     " mbarrier.try_wait.parity.acquire.cta.shared::cta.b64 P1, [%0], %1, 0x989680;" \
                     " @P1 bra.uni WD_%=; bra.uni WL_%=; WD_%=: }"                   \
                     :: "r"(_m), "r"(_p) : "memory");                                \
    }                                                                                \
} while (0)

// ---- prepass: clusters fp32 -> f16 chunk-blocked + SW128-swizzled, plus c2 norms ----
__global__ void prep_c_kernel(const float* __restrict__ C) {
    int w = (blockIdx.x * blockDim.x + threadIdx.x) >> 5;  // one warp per cluster row
    int lane = threadIdx.x & 31;
    if (w >= K_CL) return;
    const float4* src = reinterpret_cast<const float4*>(C + (size_t)w * D_DIM);
    float s = 0.f;
#pragma unroll
    for (int i = 0; i < 4; i++) {
        int f4 = lane + 32 * i;
        float4 v = src[f4];
        s += v.x * v.x + v.y * v.y + v.z * v.z + v.w * v.w;
        __half2 h0 = __float22half2_rn(make_float2(v.x, v.y));
        __half2 h1 = __float22half2_rn(make_float2(v.z, v.w));
        int col = f4 * 4;
        int chunk = col >> 6, kin = col & 63;
        uint32_t off = (uint32_t)chunk * CB_CHUNK_BYTES + sw128((uint32_t)w * 128 + kin * 2);
        *reinterpret_cast<uint2*>(g_cb + off) =
            make_uint2(*(uint32_t*)&h0, *(uint32_t*)&h1);
    }
#pragma unroll
    for (int o = 16; o; o >>= 1) s += __shfl_xor_sync(0xffffffffu, s, o);
    if (lane == 0) g_c2[w] = s;
}

// ---- main fused kernel: BM=128, 8 warps (2Mx4N), warp tile 64x64, f16 acc ----
extern __shared__ char smem[];

__global__ __launch_bounds__(256, 2)
void cluster_q_kernel(const float* __restrict__ X, float* __restrict__ out) {
    const int tid = threadIdx.x;
    const int lane = tid & 31;
    const int w = tid >> 5, wm = w >> 2, wn = w & 3;  // wm in {0,1}, wn in 0..3
    const int rowBase = blockIdx.x * BM;
    const uint32_t sb = smem_u32(smem);
    const unsigned long long gcb = gptr(g_cb);

    if (tid == 0) {
        MBAR_INIT(sb + SM_MBAR0, 1);
        MBAR_INIT(sb + SM_MBAR1, 1);
    }
    ((float*)(smem + OFF_C2S))[tid] = g_c2[tid];

    // A-load mapping: 2 threads per row; each handles 8 float4 per chunk in 2 batches of 4
    const int ar = tid >> 1;          // 0..127
    const int af = tid & 1;
    const float4* Xg =
        reinterpret_cast<const float4*>(X + (size_t)(rowBase + ar) * D_DIM) + af * 8;

    // hoisted swizzled fragment base offsets; per-ks address = q ^ kb
    uint32_t qA[4], qB[4];
    {
        const uint32_t t16a = (lane >> 4) * 16;
        const uint32_t t16b = ((lane >> 3) & 1) * 16;
#pragma unroll
        for (int mi = 0; mi < 4; mi++) {
            uint32_t row = wm * 64 + mi * 16 + ((lane >> 3) & 1) * 8 + (lane & 7);
            uint32_t base = row * 128;
            qA[mi] = base + (t16a ^ ((base >> 3) & 0x70));
        }
#pragma unroll
        for (int nt = 0; nt < 4; nt++) {
            uint32_t row = wn * 64 + nt * 16 + ((lane >> 4) & 1) * 8 + (lane & 7);
            uint32_t base = row * 128;
            qB[nt] = base + (t16b ^ ((base >> 3) & 0x70));
        }
    }

    uint32_t acc[4][8][2];   // f16x2 pairs: 64 regs
#pragma unroll
    for (int a = 0; a < 4; a++)
#pragma unroll
        for (int b = 0; b < 8; b++) { acc[a][b][0] = 0u; acc[a][b][1] = 0u; }
    float rsx = 0.f;
    float4 xv[4];

    auto loadXh = [&](int chunk, int half) {
#pragma unroll
        for (int i = 0; i < 4; i++) xv[i] = Xg[chunk * 16 + half * 4 + i];
    };
    auto storeAh = [&](uint32_t bufoff, int half) {
#pragma unroll
        for (int i = 0; i < 4; i++) {
            float4 v = xv[i];
            rsx = fmaf(v.x, v.x, fmaf(v.y, v.y, fmaf(v.z, v.z, fmaf(v.w, v.w, rsx))));
            __half2 h0 = __float22half2_rn(make_float2(v.x, v.y));
            __half2 h1 = __float22half2_rn(make_float2(v.z, v.w));
            uint32_t off = sw128((uint32_t)ar * 128 + (af * 8 + half * 4 + i) * 8);
            *reinterpret_cast<uint2*>(smem + bufoff + off) =
                make_uint2(*(uint32_t*)&h0, *(uint32_t*)&h1);
        }
    };
    auto mmaHalf = [&](uint32_t aoff, uint32_t boff, int ksBase) {
#pragma unroll
        for (int k = 0; k < 2; k++) {
            const uint32_t kb = (ksBase + k) * 32;
            uint32_t afr[4][4];
#pragma unroll
            for (int mi = 0; mi < 4; mi++) ldsm_x4(afr[mi], sb + aoff + (qA[mi] ^ kb));
#pragma unroll
            for (int nt = 0; nt < 4; nt++) {
                uint32_t bfr[4];
                ldsm_x4(bfr, sb + boff + (qB[nt] ^ kb));
#pragma unroll
                for (int mi = 0; mi < 4; mi++) {
                    mma16816h(acc[mi][2 * nt], afr[mi], bfr[0], bfr[1]);
                    mma16816h(acc[mi][2 * nt + 1], afr[mi], bfr[2], bfr[3]);
                }
            }
        }
    };

    // prologue: mbar init visible, bulk-fill B0, convert A0 (both halves)
    __syncthreads();
    if (tid == 0) {
        MBAR_EXPECT_TX(sb + SM_MBAR0, CB_CHUNK_BYTES);
        BULK_G2S(sb + OFF_B0, gcb, CB_CHUNK_BYTES, sb + SM_MBAR0);
    }
    loadXh(0, 0); storeAh(OFF_A0, 0);
    loadXh(0, 1); storeAh(OFF_A0, 1);
    __syncthreads();   // A0 visible

    for (int chunk = 0; chunk < NCHUNK; chunk++) {
        const uint32_t ao = (chunk & 1) ? OFF_A1 : OFF_A0;
        const uint32_t bo = (chunk & 1) ? OFF_B1 : OFF_B0;
        const uint32_t ano = (chunk & 1) ? OFF_A0 : OFF_A1;
        const uint32_t bno = (chunk & 1) ? OFF_B0 : OFF_B1;
        const uint32_t mcur = sb + ((chunk & 1) ? SM_MBAR1 : SM_MBAR0);
        const uint32_t mnext = sb + ((chunk & 1) ? SM_MBAR0 : SM_MBAR1);

        // issue next bulk BEFORE waiting: bno & mnext were last touched before the
        // previous chunk's __syncthreads -> safe to re-arm/refill now
        if (chunk + 1 < NCHUNK && tid == 0) {
            MBAR_EXPECT_TX(mnext, CB_CHUNK_BYTES);
            BULK_G2S(sb + bno, gcb + (unsigned long long)(chunk + 1) * CB_CHUNK_BYTES,
                     CB_CHUNK_BYTES, mnext);
        }
        MBAR_WAIT(mcur, (chunk >> 1) & 1);

        if (chunk + 1 < NCHUNK) loadXh(chunk + 1, 0);
        mmaHalf(ao, bo, 0);
        if (chunk + 1 < NCHUNK) { storeAh(ano, 0); loadXh(chunk + 1, 1); }
        mmaHalf(ao, bo, 2);
        if (chunk + 1 < NCHUNK) storeAh(ano, 1);
        __syncthreads();
    }

    // x2 norms: 2 threads share row ar
    rsx += __shfl_xor_sync(0xffffffffu, rsx, 1);
    float* x2s = (float*)(smem + OFF_X2S);
    if (af == 0) x2s[ar] = rsx;
    __syncthreads();

    // ---- epilogue phase 1: q from f16 acc + row partial sums ----
    float* c2s = (float*)(smem + OFF_C2S);
    float* part = (float*)(smem + OFF_PART);   // [128][4]
    float* invs = (float*)(smem + OFF_INV);

#pragma unroll
    for (int mi = 0; mi < 4; mi++) {
        const int r0 = wm * 64 + mi * 16 + (lane >> 2);
        const float xr0 = x2s[r0];
        const float xr1 = x2s[r0 + 8];
        float p0 = 0.f, p1 = 0.f;
#pragma unroll
        for (int ni = 0; ni < 8; ni++) {
            const int col = wn * 64 + ni * 8 + 2 * (lane & 3);
            const float c20 = c2s[col], c21 = c2s[col + 1];
            float2 v0 = __half22float2(*reinterpret_cast<__half2*>(&acc[mi][ni][0]));
            float2 v1 = __half22float2(*reinterpret_cast<__half2*>(&acc[mi][ni][1]));
            p0 += frcp(1.f + fmaxf(fmaf(-2.f, v0.x, xr0 + c20), 0.f));
            p0 += frcp(1.f + fmaxf(fmaf(-2.f, v0.y, xr0 + c21), 0.f));
            p1 += frcp(1.f + fmaxf(fmaf(-2.f, v1.x, xr1 + c20), 0.f));
            p1 += frcp(1.f + fmaxf(fmaf(-2.f, v1.y, xr1 + c21), 0.f));
        }
        p0 += __shfl_xor_sync(0xffffffffu, p0, 1);
        p0 += __shfl_xor_sync(0xffffffffu, p0, 2);
        p1 += __shfl_xor_sync(0xffffffffu, p1, 1);
        p1 += __shfl_xor_sync(0xffffffffu, p1, 2);
        if ((lane & 3) == 0) {
            part[r0 * 4 + wn] = p0;
            part[(r0 + 8) * 4 + wn] = p1;
        }
    }
    __syncthreads();
    if (tid < 128)
        invs[tid] = frcp(part[tid * 4] + part[tid * 4 + 1] + part[tid * 4 + 2] + part[tid * 4 + 3]);
    __syncthreads();

    // ---- epilogue phase 2: recompute q, scale, direct fragment stores ----
#pragma unroll
    for (int mi = 0; mi < 4; mi++) {
        const int r0 = wm * 64 + mi * 16 + (lane >> 2);
        const float xr0 = x2s[r0];
        const float xr1 = x2s[r0 + 8];
        const float iv0 = invs[r0];
        const float iv1 = invs[r0 + 8];
        float* orow0 = out + (size_t)(rowBase + r0) * K_CL;
        float* orow1 = out + (size_t)(rowBase + r0 + 8) * K_CL;
#pragma unroll
        for (int ni = 0; ni < 8; ni++) {
            const int col = wn * 64 + ni * 8 + 2 * (lane & 3);
            const float c20 = c2s[col], c21 = c2s[col + 1];
            float2 v0 = __half22float2(*reinterpret_cast<__half2*>(&acc[mi][ni][0]));
            float2 v1 = __half22float2(*reinterpret_cast<__half2*>(&acc[mi][ni][1]));
            float q00 = frcp(1.f + fmaxf(fmaf(-2.f, v0.x, xr0 + c20), 0.f));
            float q01 = frcp(1.f + fmaxf(fmaf(-2.f, v0.y, xr0 + c21), 0.f));
            float q10 = frcp(1.f + fmaxf(fmaf(-2.f, v1.x, xr1 + c20), 0.f));
            float q11 = frcp(1.f + fmaxf(fmaf(-2.f, v1.y, xr1 + c21), 0.f));
            *reinterpret_cast<float2*>(&orow0[col]) = make_float2(q00 * iv0, q01 * iv0);
            *reinterpret_cast<float2*>(&orow1[col]) = make_float2(q10 * iv1, q11 * iv1);
        }
    }
}

extern "C" void kernel_launch(void* const* d_in, const int* in_sizes, int n_in,
                              void* d_out, int out_size) {
    const float* X = (const float*)d_in[0];   // [65536, 512]
    const float* C = (const float*)d_in[1];   // [256, 512]
    float* out = (float*)d_out;               // [65536, 256]
    const int n = in_sizes[0] / D_DIM;

    cudaFuncSetAttribute(cluster_q_kernel, cudaFuncAttributeMaxDynamicSharedMemorySize,
                         SMEM_TOTAL);
    prep_c_kernel<<<32, 256>>>(C);
    cluster_q_kernel<<<n / BM, 256, SMEM_TOTAL>>>(X, out);
}

// round 11
// speedup vs baseline: 1.6207x; 1.6207x over previous
#include <cuda_runtime.h>
#include <cuda_fp16.h>
#include <cstdint>

// N=65536, K=256, D=512, ALPHA=1, fp32 in/out.
#define D_DIM  512
#define K_CL   256
#define BM     64
#define KC     64
#define NCHUNK 8
#define CB_CHUNK_BYTES (K_CL * KC * 2)   // 32768

// smem byte offsets
#define OFF_A0   0        // 64 x 128B  = 8192
#define OFF_A1   8192
#define OFF_B0   16384    // 256 x 128B = 32768
#define OFF_B1   49152
#define OFF_C2S  81920    // 256 f32
#define OFF_X2S  82944    // 64 f32
#define OFF_PART 83200    // 64*4 f32
#define OFF_INV  84224    // 64 f32
#define SM_MBAR0 84480
#define SM_MBAR1 84488
#define SMEM_TOTAL 84608

__device__ __align__(128) unsigned char g_cb[NCHUNK * CB_CHUNK_BYTES]; // 256KB f16 swizzled
__device__ float g_c2[K_CL];

__device__ __forceinline__ uint32_t sw128(uint32_t off) { return off ^ ((off >> 3) & 0x70); }

__device__ __forceinline__ uint32_t smem_u32(const void* p) {
    uint32_t a;
    asm("{ .reg .u64 t; cvta.to.shared.u64 t, %1; cvt.u32.u64 %0, t; }" : "=r"(a) : "l"(p));
    return a;
}
__device__ __forceinline__ unsigned long long gptr(const void* p) {
    unsigned long long a;
    asm("cvta.to.global.u64 %0, %1;" : "=l"(a) : "l"(p));
    return a;
}
__device__ __forceinline__ float frcp(float x) {
    float r; asm("rcp.approx.f32 %0, %1;" : "=f"(r) : "f"(x)); return r;
}
__device__ __forceinline__ void ldsm_x4(uint32_t (&r)[4], uint32_t addr) {
    asm volatile("ldmatrix.sync.aligned.m8n8.x4.shared.b16 {%0,%1,%2,%3}, [%4];"
                 : "=r"(r[0]), "=r"(r[1]), "=r"(r[2]), "=r"(r[3]) : "r"(addr));
}
// f16 accumulate: d = 2 b32 regs; d[0] = (c0,c1) of row, d[1] = (c0,c1) of row+8
__device__ __forceinline__ void mma16816h(uint32_t (&d)[2], const uint32_t (&a)[4],
                                          uint32_t b0, uint32_t b1) {
    asm volatile("mma.sync.aligned.m16n8k16.row.col.f16.f16.f16.f16 "
                 "{%0,%1}, {%2,%3,%4,%5}, {%6,%7}, {%0,%1};"
                 : "+r"(d[0]), "+r"(d[1])
                 : "r"(a[0]), "r"(a[1]), "r"(a[2]), "r"(a[3]), "r"(b0), "r"(b1));
}

#define MBAR_INIT(a, c) \
    asm volatile("mbarrier.init.shared.b64 [%0], %1;" :: "r"(a), "r"(c) : "memory")
#define MBAR_EXPECT_TX(a, n) \
    asm volatile("mbarrier.arrive.expect_tx.shared.b64 _, [%0], %1;" :: "r"(a), "r"(n) : "memory")
#define BULK_G2S(dst, src, n, mbar) \
    asm volatile("cp.async.bulk.shared::cluster.global.mbarrier::complete_tx::bytes " \
                 "[%0], [%1], %2, [%3];" \
                 :: "r"(dst), "l"(src), "r"(n), "r"(mbar) : "memory")
#define MBAR_WAIT(a, ph) do {                                                        \
    uint32_t _m = (a), _p = (ph), _d;                                                \
    asm volatile("{ .reg .pred p; mbarrier.try_wait.parity.acquire.cta.shared::cta.b64 p, [%1], %2;" \
                 " selp.b32 %0, 1, 0, p; }" : "=r"(_d) : "r"(_m), "r"(_p) : "memory"); \
    if (!_d) {                                                                       \
        asm volatile("{ .reg .pred P1; WL_%=:"                                       \
                     " mbarrier.try_wait.parity.acquire.cta.shared::cta.b64 P1, [%0], %1, 0x989680;" \
                     " @P1 bra.uni WD_%=; bra.uni WL_%=; WD_%=: }"                   \
                     :: "r"(_m), "r"(_p) : "memory");                                \
    }                                                                                \
} while (0)

// ---- prepass: clusters fp32 -> f16 chunk-blocked + SW128-swizzled, plus c2 norms ----
__global__ void prep_c_kernel(const float* __restrict__ C) {
    int w = (blockIdx.x * blockDim.x + threadIdx.x) >> 5;  // one warp per cluster row
    int lane = threadIdx.x & 31;
    if (w >= K_CL) return;
    const float4* src = reinterpret_cast<const float4*>(C + (size_t)w * D_DIM);
    float s = 0.f;
#pragma unroll
    for (int i = 0; i < 4; i++) {
        int f4 = lane + 32 * i;
        float4 v = src[f4];
        s += v.x * v.x + v.y * v.y + v.z * v.z + v.w * v.w;
        __half2 h0 = __float22half2_rn(make_float2(v.x, v.y));
        __half2 h1 = __float22half2_rn(make_float2(v.z, v.w));
        int col = f4 * 4;
        int chunk = col >> 6, kin = col & 63;
        uint32_t off = (uint32_t)chunk * CB_CHUNK_BYTES + sw128((uint32_t)w * 128 + kin * 2);
        *reinterpret_cast<uint2*>(g_cb + off) =
            make_uint2(*(uint32_t*)&h0, *(uint32_t*)&h1);
    }
#pragma unroll
    for (int o = 16; o; o >>= 1) s += __shfl_xor_sync(0xffffffffu, s, o);
    if (lane == 0) g_c2[w] = s;
}

// ---- main fused kernel: BM=64, 8 warps, 32x64 warp tile, f16 acc, bulk B ----
extern __shared__ char smem[];

__global__ __launch_bounds__(256, 2)
void cluster_q_kernel(const float* __restrict__ X, float* __restrict__ out) {
    const int tid = threadIdx.x;
    const int lane = tid & 31;
    const int w = tid >> 5, wm = w >> 2, wn = w & 3;
    const int rowBase = blockIdx.x * BM;
    const uint32_t sb = smem_u32(smem);
    const unsigned long long gcb = gptr(g_cb);

    if (tid == 0) {
        MBAR_INIT(sb + SM_MBAR0, 1);
        MBAR_INIT(sb + SM_MBAR1, 1);
    }
    ((float*)(smem + OFF_C2S))[tid] = g_c2[tid];

    // A-load mapping: thread -> row ar, float4 base af; 4 float4/chunk
    const int ar = tid >> 2;
    const int af = tid & 3;
    const float4* Xg = reinterpret_cast<const float4*>(X + (size_t)(rowBase + ar) * D_DIM) + af;

    // hoisted swizzled fragment base offsets; per-ks address = q ^ kb
    uint32_t qA[2], qB[4];
    {
        const uint32_t t16a = (lane >> 4) * 16;
        const uint32_t t16b = ((lane >> 3) & 1) * 16;
#pragma unroll
        for (int mi = 0; mi < 2; mi++) {
            uint32_t row = wm * 32 + mi * 16 + ((lane >> 3) & 1) * 8 + (lane & 7);
            uint32_t base = row * 128;
            qA[mi] = base + (t16a ^ ((base >> 3) & 0x70));
        }
#pragma unroll
        for (int nt = 0; nt < 4; nt++) {
            uint32_t row = wn * 64 + nt * 16 + ((lane >> 4) & 1) * 8 + (lane & 7);
            uint32_t base = row * 128;
            qB[nt] = base + (t16b ^ ((base >> 3) & 0x70));
        }
    }

    uint32_t acc[2][8][2];   // f16x2 pairs: 32 regs
#pragma unroll
    for (int a = 0; a < 2; a++)
#pragma unroll
        for (int b = 0; b < 8; b++) { acc[a][b][0] = 0u; acc[a][b][1] = 0u; }
    float rsx = 0.f;
    float4 xv[4];

    auto loadX = [&](int chunk) {
#pragma unroll
        for (int i = 0; i < 4; i++) xv[i] = Xg[chunk * 16 + 4 * i];
    };
    auto storeA = [&](uint32_t bufoff) {
#pragma unroll
        for (int i = 0; i < 4; i++) {
            float4 v = xv[i];
            rsx = fmaf(v.x, v.x, fmaf(v.y, v.y, fmaf(v.z, v.z, fmaf(v.w, v.w, rsx))));
            __half2 h0 = __float22half2_rn(make_float2(v.x, v.y));
            __half2 h1 = __float22half2_rn(make_float2(v.z, v.w));
            uint32_t off = sw128((uint32_t)ar * 128 + (af + 4 * i) * 8);
            *reinterpret_cast<uint2*>(smem + bufoff + off) =
                make_uint2(*(uint32_t*)&h0, *(uint32_t*)&h1);
        }
    };
    auto mmaChunk = [&](uint32_t aoff, uint32_t boff) {
#pragma unroll
        for (int ks = 0; ks < 4; ks++) {
            const uint32_t kb = ks * 32;
            uint32_t afr[2][4];
#pragma unroll
            for (int mi = 0; mi < 2; mi++) ldsm_x4(afr[mi], sb + aoff + (qA[mi] ^ kb));
#pragma unroll
            for (int nt = 0; nt < 4; nt++) {
                uint32_t bfr[4];
                ldsm_x4(bfr, sb + boff + (qB[nt] ^ kb));
#pragma unroll
                for (int mi = 0; mi < 2; mi++) {
                    mma16816h(acc[mi][2 * nt], afr[mi], bfr[0], bfr[1]);
                    mma16816h(acc[mi][2 * nt + 1], afr[mi], bfr[2], bfr[3]);
                }
            }
        }
    };

    // prologue: mbar init visible, bulk-fill B0, convert A0
    __syncthreads();
    if (tid == 0) {
        MBAR_EXPECT_TX(sb + SM_MBAR0, CB_CHUNK_BYTES);
        BULK_G2S(sb + OFF_B0, gcb, CB_CHUNK_BYTES, sb + SM_MBAR0);
    }
    loadX(0);
    storeA(OFF_A0);
    __syncthreads();   // A0 visible

    for (int chunk = 0; chunk < NCHUNK; chunk++) {
        const uint32_t ao = (chunk & 1) ? OFF_A1 : OFF_A0;
        const uint32_t bo = (chunk & 1) ? OFF_B1 : OFF_B0;
        const uint32_t ano = (chunk & 1) ? OFF_A0 : OFF_A1;
        const uint32_t bno = (chunk & 1) ? OFF_B0 : OFF_B1;
        const uint32_t mcur = sb + ((chunk & 1) ? SM_MBAR1 : SM_MBAR0);
        const uint32_t mnext = sb + ((chunk & 1) ? SM_MBAR0 : SM_MBAR1);

        // issue next bulk + X LDGs BEFORE waiting: bno/mnext last touched before the
        // previous chunk's __syncthreads -> safe; LDGs gain flight time under the wait
        if (chunk + 1 < NCHUNK) {
            if (tid == 0) {
                MBAR_EXPECT_TX(mnext, CB_CHUNK_BYTES);
                BULK_G2S(sb + bno, gcb + (unsigned long long)(chunk + 1) * CB_CHUNK_BYTES,
                         CB_CHUNK_BYTES, mnext);
            }
            loadX(chunk + 1);
        }
        MBAR_WAIT(mcur, (chunk >> 1) & 1);

        mmaChunk(ao, bo);
        if (chunk + 1 < NCHUNK) storeA(ano);
        __syncthreads();
    }

    // x2 norms: 4 lanes share row ar
    rsx += __shfl_xor_sync(0xffffffffu, rsx, 1);
    rsx += __shfl_xor_sync(0xffffffffu, rsx, 2);
    float* x2s = (float*)(smem + OFF_X2S);
    if ((tid & 3) == 0) x2s[ar] = rsx;
    __syncthreads();

    // ---- epilogue phase 1: q from f16 acc + row partial sums ----
    float* c2s = (float*)(smem + OFF_C2S);
    float* part = (float*)(smem + OFF_PART);   // [64][4]
    float* invs = (float*)(smem + OFF_INV);

    float qv[2][8][4];
#pragma unroll
    for (int mi = 0; mi < 2; mi++) {
        const int r0 = wm * 32 + mi * 16 + (lane >> 2);
        const float xr0 = x2s[r0];
        const float xr1 = x2s[r0 + 8];
        float p0 = 0.f, p1 = 0.f;
#pragma unroll
        for (int ni = 0; ni < 8; ni++) {
            const int col = wn * 64 + ni * 8 + 2 * (lane & 3);
            const float c20 = c2s[col], c21 = c2s[col + 1];
            float2 v0 = __half22float2(*reinterpret_cast<__half2*>(&acc[mi][ni][0]));
            float2 v1 = __half22float2(*reinterpret_cast<__half2*>(&acc[mi][ni][1]));
            float q00 = frcp(1.f + fmaxf(fmaf(-2.f, v0.x, xr0 + c20), 0.f));
            float q01 = frcp(1.f + fmaxf(fmaf(-2.f, v0.y, xr0 + c21), 0.f));
            float q10 = frcp(1.f + fmaxf(fmaf(-2.f, v1.x, xr1 + c20), 0.f));
            float q11 = frcp(1.f + fmaxf(fmaf(-2.f, v1.y, xr1 + c21), 0.f));
            p0 += q00 + q01;
            p1 += q10 + q11;
            qv[mi][ni][0] = q00; qv[mi][ni][1] = q01;
            qv[mi][ni][2] = q10; qv[mi][ni][3] = q11;
        }
        p0 += __shfl_xor_sync(0xffffffffu, p0, 1);
        p0 += __shfl_xor_sync(0xffffffffu, p0, 2);
        p1 += __shfl_xor_sync(0xffffffffu, p1, 1);
        p1 += __shfl_xor_sync(0xffffffffu, p1, 2);
        if ((lane & 3) == 0) {
            part[r0 * 4 + wn] = p0;
            part[(r0 + 8) * 4 + wn] = p1;
        }
    }
    __syncthreads();
    if (tid < 64)
        invs[tid] = frcp(part[tid * 4] + part[tid * 4 + 1] + part[tid * 4 + 2] + part[tid * 4 + 3]);
    __syncthreads();

    // ---- epilogue phase 2: direct fragment stores ----
#pragma unroll
    for (int mi = 0; mi < 2; mi++) {
        const int r0 = wm * 32 + mi * 16 + (lane >> 2);
        const float iv0 = invs[r0];
        const float iv1 = invs[r0 + 8];
        float* orow0 = out + (size_t)(rowBase + r0) * K_CL;
        float* orow1 = out + (size_t)(rowBase + r0 + 8) * K_CL;
#pragma unroll
        for (int ni = 0; ni < 8; ni++) {
            const int col = wn * 64 + ni * 8 + 2 * (lane & 3);
            *reinterpret_cast<float2*>(&orow0[col]) =
                make_float2(qv[mi][ni][0] * iv0, qv[mi][ni][1] * iv0);
            *reinterpret_cast<float2*>(&orow1[col]) =
                make_float2(qv[mi][ni][2] * iv1, qv[mi][ni][3] * iv1);
        }
    }
}

extern "C" void kernel_launch(void* const* d_in, const int* in_sizes, int n_in,
                              void* d_out, int out_size) {
    const float* X = (const float*)d_in[0];   // [65536, 512]
    const float* C = (const float*)d_in[1];   // [256, 512]
    float* out = (float*)d_out;               // [65536, 256]
    const int n = in_sizes[0] / D_DIM;

    cudaFuncSetAttribute(cluster_q_kernel, cudaFuncAttributeMaxDynamicSharedMemorySize,
                         SMEM_TOTAL);
    prep_c_kernel<<<32, 256>>>(C);
    cluster_q_kernel<<<n / BM, 256, SMEM_TOTAL>>>(X, out);
}